// round 8
// baseline (speedup 1.0000x reference)
#include <cuda_runtime.h>
#include <math.h>

#define Bb   4
#define Ls   1024
#define Hh   768
#define NHh  12
#define NEe  30
#define Mm   6
#define Pp   600
#define EMBe 768
#define NCc  97
#define K2H  1536           // 2*H
#define QQ   12288          // EMB*BS
#define BP   (Bb*Pp)        // 2400
#define BE   (Bb*NEe)       // 120
#define EKC  3              // K-chunks for E gemm
#define BLKS 8              // bilinear K-split

typedef unsigned long long u64;

__device__ __forceinline__ u64 ffma2(u64 a, u64 b, u64 c) {
    u64 d; asm("fma.rn.f32x2 %0,%1,%2,%3;" : "=l"(d) : "l"(a), "l"(b), "l"(c)); return d;
}
__device__ __forceinline__ u64 dupf(float x) {
    u64 d; asm("mov.b64 %0,{%1,%1};" : "=l"(d) : "f"(x)); return d;
}
__device__ __forceinline__ float lo32(u64 v) { return __uint_as_float((unsigned)v); }
__device__ __forceinline__ float hi32(u64 v) { return __uint_as_float((unsigned)(v >> 32)); }

// ---------------- scratch ----------------
__device__ float g_e_emb[BE*Hh];
__device__ float g_e_att[BE*NHh*Ls];
__device__ float g_ht  [BP*Ls];
__device__ float g_rsp [2*BP*Hh];          // rs partials [kc][b][p][h]
__device__ float g_R   [2*BP*Hh];          // [side][m][e]
__device__ float g_Ep  [EKC*2*BE*Hh];
__device__ float g_hs  [BP*EMBe];
__device__ float g_ts  [BP*EMBe];
__device__ float g_Wcp [2*NCc*QQ];         // Wc partials
__device__ float g_WcT [QQ*128];           // transposed+merged, c padded to 128
__device__ float g_blp [BP*BLKS*128];      // bilinear partials [m][kc][c]

// ---------------- kernel 1: entity pooling (vectorized) ----------------
__global__ void pool_kernel(const float* __restrict__ seq,
                            const float* __restrict__ att,
                            const float* __restrict__ mmask,
                            const int*   __restrict__ midx)
{
    int be = blockIdx.x;
    int b = be / NEe;
    __shared__ int   idx[Mm];
    __shared__ float msk[Mm];
    if (threadIdx.x < Mm) {
        idx[threadIdx.x] = midx[be*Mm + threadIdx.x];
        msk[threadIdx.x] = mmask[be*Mm + threadIdx.x];
    }
    __syncthreads();
    float cnt = 0.f;
    #pragma unroll
    for (int m = 0; m < Mm; m++) cnt += msk[m];
    cnt = fmaxf(cnt, 1.0f);
    float invc = 1.0f / cnt;

    for (int h = threadIdx.x; h < Hh; h += blockDim.x) {
        float v[Mm]; float mx = -1e30f;
        #pragma unroll
        for (int m = 0; m < Mm; m++) {
            float x = seq[((long)b*Ls + idx[m])*Hh + h];
            x = (msk[m] > 0.f) ? x : -1e30f;
            v[m] = x; mx = fmaxf(mx, x);
        }
        float s = 0.f;
        #pragma unroll
        for (int m = 0; m < Mm; m++) s += expf(v[m] - mx);
        g_e_emb[(long)be*Hh + h] = mx + logf(s);
    }
    for (int t = threadIdx.x; t < NHh*(Ls/4); t += blockDim.x) {
        int nh = t >> 8, lq = (t & 255)*4;
        float4 s4 = make_float4(0.f,0.f,0.f,0.f);
        #pragma unroll
        for (int m = 0; m < Mm; m++) {
            float4 a = *(const float4*)&att[(((long)b*NHh + nh)*Ls + idx[m])*Ls + lq];
            float w = msk[m];
            s4.x += a.x*w; s4.y += a.y*w; s4.z += a.z*w; s4.w += a.w*w;
        }
        s4.x *= invc; s4.y *= invc; s4.z *= invc; s4.w *= invc;
        *(float4*)&g_e_att[((long)be*NHh + nh)*Ls + lq] = s4;
    }
}

// ---------------- kernel 2: pairwise attention mix (float4) ----------------
__global__ void htatt_kernel(const int* __restrict__ hts)
{
    int bp = blockIdx.x;
    int b = bp / Pp;
    int he = hts[bp*2 + 0];
    int te = hts[bp*2 + 1];
    const float* ha = &g_e_att[((long)(b*NEe + he))*NHh*Ls];
    const float* ta = &g_e_att[((long)(b*NEe + te))*NHh*Ls];
    __shared__ float sv[Ls];
    __shared__ float red[256];
    int lq = threadIdx.x * 4;
    float4 s4 = make_float4(0.f,0.f,0.f,0.f);
    #pragma unroll
    for (int nh = 0; nh < NHh; nh++) {
        float4 a = *(const float4*)&ha[nh*Ls + lq];
        float4 t = *(const float4*)&ta[nh*Ls + lq];
        s4.x += a.x*t.x; s4.y += a.y*t.y; s4.z += a.z*t.z; s4.w += a.w*t.w;
    }
    const float inh = 1.0f / NHh;
    s4.x *= inh; s4.y *= inh; s4.z *= inh; s4.w *= inh;
    *(float4*)&sv[lq] = s4;
    red[threadIdx.x] = s4.x + s4.y + s4.z + s4.w;
    for (int o = 128; o > 0; o >>= 1) {
        __syncthreads();
        if (threadIdx.x < o) red[threadIdx.x] += red[threadIdx.x + o];
    }
    __syncthreads();
    float inv = 1.0f / (red[0] + 1e-30f);
    float4 v = *(const float4*)&sv[lq];
    v.x *= inv; v.y *= inv; v.z *= inv; v.w *= inv;
    *(float4*)&g_ht[(long)bp*Ls + lq] = v;
}

// ======== FFMA2 inner-loop macro: m-paired, b dup'd in regs ========
// Requires: As/Bs [2][8][132] float smem, tm, tn, buf, acc (u64[4][8]).
#define FFMA2_TILE_STEP(ASrc, BSrc)                                          \
    _Pragma("unroll")                                                        \
    for (int kk = 0; kk < 8; kk++) {                                         \
        ulonglong2 a01 = *(const ulonglong2*)&ASrc[kk][tm*8];                \
        ulonglong2 a23 = *(const ulonglong2*)&ASrc[kk][tm*8+4];              \
        u64 ap[4] = {a01.x, a01.y, a23.x, a23.y};                            \
        float bsc[8];                                                        \
        *(float4*)&bsc[0] = *(const float4*)&BSrc[kk][tn*8];                 \
        *(float4*)&bsc[4] = *(const float4*)&BSrc[kk][tn*8+4];               \
        u64 bd[8];                                                           \
        _Pragma("unroll")                                                    \
        for (int j = 0; j < 8; j++) bd[j] = dupf(bsc[j]);                    \
        _Pragma("unroll")                                                    \
        for (int i = 0; i < 4; i++)                                          \
            _Pragma("unroll")                                                \
            for (int j = 0; j < 8; j++)                                      \
                acc[i][j] = ffma2(ap[i], bd[j], acc[i][j]);                  \
    }

// ---------------- 128x128 NN GEMM, FFMA2, double-buffered, K-split ----------
// z = bz*ksplit + kc. Partial C layout [kc][bz][M][N] (stride sC per (kc,bz)).
__global__ __launch_bounds__(256) void gemm_nn128(
    const float* __restrict__ A, const float* __restrict__ B, float* __restrict__ C,
    int M, int N, int K, long sA, long sB, long sC, int ksplit)
{
    __shared__ __align__(16) float As[2][8][132];
    __shared__ __align__(16) float Bs[2][8][132];
    int z = blockIdx.z;
    int kc = z % ksplit;
    int bz = z / ksplit;
    int nbz = gridDim.z / ksplit;
    int klen = K / ksplit;
    int kbeg = kc * klen, kend = kbeg + klen;
    const float* Ab = A + (long)bz*sA;
    const float* Bp = B + (long)bz*sB;
    float*       Cb = C + ((long)kc*nbz + bz)*sC;
    int m0 = blockIdx.x*128, n0 = blockIdx.y*128;
    int tid = threadIdx.x;

    int ar = tid >> 1, akq = (tid & 1)*4;
    int am = m0 + ar; if (am > M-1) am = M-1;
    int bkr = tid >> 5, bnq = (tid & 31)*4;
    const float* aptr = Ab + (long)am*K + kbeg + akq;
    const float* bptr = Bp + (long)(kbeg + bkr)*N + n0 + bnq;

    float4 av = *(const float4*)aptr;
    float4 bv = *(const float4*)bptr;

    int tm = tid & 15, tn = tid >> 4;
    u64 acc[4][8];
    #pragma unroll
    for (int i = 0; i < 4; i++)
        #pragma unroll
        for (int j = 0; j < 8; j++) acc[i][j] = 0ULL;
    int buf = 0;
    As[0][akq+0][ar] = av.x; As[0][akq+1][ar] = av.y;
    As[0][akq+2][ar] = av.z; As[0][akq+3][ar] = av.w;
    *(float4*)&Bs[0][bkr][bnq] = bv;
    __syncthreads();

    for (int k0 = kbeg; k0 < kend; k0 += 8) {
        bool next = (k0 + 8 < kend);
        if (next) {
            aptr += 8; bptr += (long)8*N;
            av = *(const float4*)aptr;
            bv = *(const float4*)bptr;
        }
        FFMA2_TILE_STEP(As[buf], Bs[buf])
        if (next) {
            int nb = buf ^ 1;
            As[nb][akq+0][ar] = av.x; As[nb][akq+1][ar] = av.y;
            As[nb][akq+2][ar] = av.z; As[nb][akq+3][ar] = av.w;
            *(float4*)&Bs[nb][bkr][bnq] = bv;
            __syncthreads();
            buf = nb;
        }
    }
    #pragma unroll
    for (int i = 0; i < 4; i++) {
        int m = m0 + tm*8 + 2*i;
        if (m < M) {
            float4 o0 = make_float4(lo32(acc[i][0]), lo32(acc[i][1]), lo32(acc[i][2]), lo32(acc[i][3]));
            float4 o1 = make_float4(lo32(acc[i][4]), lo32(acc[i][5]), lo32(acc[i][6]), lo32(acc[i][7]));
            *(float4*)&Cb[(long)m*N + n0 + tn*8    ] = o0;
            *(float4*)&Cb[(long)m*N + n0 + tn*8 + 4] = o1;
        }
        if (m + 1 < M) {
            float4 o0 = make_float4(hi32(acc[i][0]), hi32(acc[i][1]), hi32(acc[i][2]), hi32(acc[i][3]));
            float4 o1 = make_float4(hi32(acc[i][4]), hi32(acc[i][5]), hi32(acc[i][6]), hi32(acc[i][7]));
            *(float4*)&Cb[(long)(m+1)*N + n0 + tn*8    ] = o0;
            *(float4*)&Cb[(long)(m+1)*N + n0 + tn*8 + 4] = o1;
        }
    }
}

// ---------------- Wc merge + transpose: g_WcT[q][c] = p0+p1 ----------------
__global__ void wct_kernel()
{
    __shared__ float sm[32][33];
    int q0 = blockIdx.x * 32;
    int c0 = blockIdx.y * 32;
    int tx = threadIdx.x, ty = threadIdx.y;    // (32, 8)
    #pragma unroll
    for (int u = 0; u < 4; u++) {
        int c = c0 + ty + u*8;
        float v = 0.f;
        if (c < NCc) {
            long o = (long)c*QQ + q0 + tx;
            v = g_Wcp[o] + g_Wcp[(long)NCc*QQ + o];
        }
        sm[ty + u*8][tx] = v;
    }
    __syncthreads();
    #pragma unroll
    for (int u = 0; u < 4; u++) {
        int q = q0 + ty + u*8;
        g_WcT[(long)q*128 + c0 + tx] = sm[tx][ty + u*8];
    }
}

// ---------------- R GEMM (NT, FFMA2): g_R[side] = (rsp0+rsp1) @ W[:,768:]^T --
__global__ __launch_bounds__(256) void r_gemm(
    const float* __restrict__ headW, const float* __restrict__ tailW)
{
    __shared__ __align__(16) float As[2][8][132];
    __shared__ __align__(16) float Bs[2][8][132];
    int side = blockIdx.z;
    const float* W = side ? tailW : headW;
    float* Cb = g_R + (long)side*BP*Hh;
    int m0 = blockIdx.x*128, n0 = blockIdx.y*128;
    int tid = threadIdx.x;

    int ar = tid >> 1, akq = (tid & 1)*4;
    int am = m0 + ar; if (am > BP-1) am = BP-1;
    int bn = tid >> 1, bkq = (tid & 1)*4;
    const float* aptr = g_rsp + (long)am*Hh + akq;
    const float* bptr = W + (long)(n0 + bn)*K2H + Hh + bkq;
    const long POFF = (long)BP*Hh;

    float4 a0 = *(const float4*)aptr;
    float4 a1 = *(const float4*)(aptr + POFF);
    float4 bv = *(const float4*)bptr;
    float4 av = make_float4(a0.x+a1.x, a0.y+a1.y, a0.z+a1.z, a0.w+a1.w);

    int tm = tid & 15, tn = tid >> 4;
    u64 acc[4][8];
    #pragma unroll
    for (int i = 0; i < 4; i++)
        #pragma unroll
        for (int j = 0; j < 8; j++) acc[i][j] = 0ULL;
    int buf = 0;
    As[0][akq+0][ar] = av.x; As[0][akq+1][ar] = av.y;
    As[0][akq+2][ar] = av.z; As[0][akq+3][ar] = av.w;
    Bs[0][bkq+0][bn] = bv.x; Bs[0][bkq+1][bn] = bv.y;
    Bs[0][bkq+2][bn] = bv.z; Bs[0][bkq+3][bn] = bv.w;
    __syncthreads();

    for (int k0 = 0; k0 < Hh; k0 += 8) {
        bool next = (k0 + 8 < Hh);
        if (next) {
            aptr += 8; bptr += 8;
            a0 = *(const float4*)aptr;
            a1 = *(const float4*)(aptr + POFF);
            bv = *(const float4*)bptr;
            av = make_float4(a0.x+a1.x, a0.y+a1.y, a0.z+a1.z, a0.w+a1.w);
        }
        FFMA2_TILE_STEP(As[buf], Bs[buf])
        if (next) {
            int nb = buf ^ 1;
            As[nb][akq+0][ar] = av.x; As[nb][akq+1][ar] = av.y;
            As[nb][akq+2][ar] = av.z; As[nb][akq+3][ar] = av.w;
            Bs[nb][bkq+0][bn] = bv.x; Bs[nb][bkq+1][bn] = bv.y;
            Bs[nb][bkq+2][bn] = bv.z; Bs[nb][bkq+3][bn] = bv.w;
            __syncthreads();
            buf = nb;
        }
    }
    #pragma unroll
    for (int i = 0; i < 4; i++) {
        int m = m0 + tm*8 + 2*i;
        if (m < BP) {
            float4 o0 = make_float4(lo32(acc[i][0]), lo32(acc[i][1]), lo32(acc[i][2]), lo32(acc[i][3]));
            float4 o1 = make_float4(lo32(acc[i][4]), lo32(acc[i][5]), lo32(acc[i][6]), lo32(acc[i][7]));
            *(float4*)&Cb[(long)m*Hh + n0 + tn*8    ] = o0;
            *(float4*)&Cb[(long)m*Hh + n0 + tn*8 + 4] = o1;
        }
        if (m + 1 < BP) {
            float4 o0 = make_float4(hi32(acc[i][0]), hi32(acc[i][1]), hi32(acc[i][2]), hi32(acc[i][3]));
            float4 o1 = make_float4(hi32(acc[i][4]), hi32(acc[i][5]), hi32(acc[i][6]), hi32(acc[i][7]));
            *(float4*)&Cb[(long)(m+1)*Hh + n0 + tn*8    ] = o0;
            *(float4*)&Cb[(long)(m+1)*Hh + n0 + tn*8 + 4] = o1;
        }
    }
}

// ---------------- E GEMM (NT, K-chunked, 64x64 tile) ----------------
__global__ __launch_bounds__(256) void e_gemm(
    const float* __restrict__ headW, const float* __restrict__ tailW)
{
    __shared__ float As[16][65];
    __shared__ float Bs[16][65];
    int z = blockIdx.z;
    int side = z & 1, kc = z >> 1;
    const float* W = side ? tailW : headW;
    float* Cb = g_Ep + (long)(kc*2 + side)*BE*Hh;
    int m0 = blockIdx.x*64, n0 = blockIdx.y*64;
    int tid = threadIdx.x;
    int tm = tid & 15, tn = tid >> 4;
    float acc[4][4] = {};
    int kbeg = kc*256, kend = kbeg + 256;
    for (int k0 = kbeg; k0 < kend; k0 += 16) {
        #pragma unroll
        for (int i = 0; i < 4; i++) {
            int idx = tid + i*256;
            int m = idx >> 4, k = idx & 15;
            int mg = m0 + m; if (mg > BE-1) mg = BE-1;
            As[k][m] = g_e_emb[(long)mg*Hh + k0 + k];
        }
        #pragma unroll
        for (int i = 0; i < 4; i++) {
            int idx = tid + i*256;
            int e = idx >> 4, k = idx & 15;
            Bs[k][e] = W[(long)(n0 + e)*K2H + k0 + k];
        }
        __syncthreads();
        #pragma unroll
        for (int kk = 0; kk < 16; kk++) {
            float a[4], bb[4];
            #pragma unroll
            for (int i = 0; i < 4; i++) a[i]  = As[kk][tm + 16*i];
            #pragma unroll
            for (int j = 0; j < 4; j++) bb[j] = Bs[kk][tn + 16*j];
            #pragma unroll
            for (int i = 0; i < 4; i++)
                #pragma unroll
                for (int j = 0; j < 4; j++)
                    acc[i][j] += a[i]*bb[j];
        }
        __syncthreads();
    }
    #pragma unroll
    for (int i = 0; i < 4; i++) {
        int m = m0 + tm + 16*i;
        if (m >= BE) continue;
        #pragma unroll
        for (int j = 0; j < 4; j++)
            Cb[(long)m*Hh + n0 + tn + 16*j] = acc[i][j];
    }
}

// ---------------- fused gather + add + tanh ----------------
__global__ void fuse_tanh(const float* __restrict__ headb,
                          const float* __restrict__ tailb,
                          const int*   __restrict__ hts)
{
    int m = blockIdx.x, side = blockIdx.y;
    int b = m / Pp;
    int ent = hts[m*2 + side];
    int er = b*NEe + ent;
    const float* Rr   = g_R + ((long)side*BP + m)*Hh;
    const float* bias = side ? tailb : headb;
    float* outp = (side ? g_ts : g_hs) + (long)m*EMBe;
    const float* e0 = g_Ep + (long)(0*2 + side)*BE*Hh + (long)er*Hh;
    const float* e1 = g_Ep + (long)(1*2 + side)*BE*Hh + (long)er*Hh;
    const float* e2 = g_Ep + (long)(2*2 + side)*BE*Hh + (long)er*Hh;
    int e = threadIdx.x * 4;
    float4 r  = *(const float4*)&Rr[e];
    float4 p0 = *(const float4*)&e0[e];
    float4 p1 = *(const float4*)&e1[e];
    float4 p2 = *(const float4*)&e2[e];
    float4 bi = *(const float4*)&bias[e];
    float4 o;
    o.x = tanhf(r.x + p0.x + p1.x + p2.x + bi.x);
    o.y = tanhf(r.y + p0.y + p1.y + p2.y + bi.y);
    o.z = tanhf(r.z + p0.z + p1.z + p2.z + bi.z);
    o.w = tanhf(r.w + p0.w + p1.w + p2.w + bi.w);
    *(float4*)&outp[e] = o;
}

// ---------------- bilinear as GEMM (FFMA2): A materialized, B = WcT ----------
__global__ __launch_bounds__(256) void bilinear_gemm()
{
    __shared__ __align__(16) float As[2][8][132];
    __shared__ __align__(16) float Bs[2][8][132];
    int kc = blockIdx.z;
    int kbeg = kc * (QQ / BLKS), kend = kbeg + (QQ / BLKS);
    int m0 = blockIdx.x*128;
    int tid = threadIdx.x;

    int ar = tid >> 1, akq = (tid & 1)*4;
    int am = m0 + ar; if (am > BP-1) am = BP-1;
    int bkr = tid >> 5, bnq = (tid & 31)*4;
    const float* bptr = g_WcT + (long)(kbeg + bkr)*128 + bnq;
    const float* hrow = g_hs + (long)am*EMBe;
    const float* trow = g_ts + (long)am*EMBe;

    int kb = kbeg >> 8, iQ = (kbeg >> 4) & 15, jb = kbeg & 8;
    float4 t4 = *(const float4*)&trow[(kb<<4) + jb + akq];
    float  hv = hrow[(kb<<4) + iQ];
    float4 av = make_float4(hv*t4.x, hv*t4.y, hv*t4.z, hv*t4.w);
    float4 bv = *(const float4*)bptr;

    int tm = tid & 15, tn = tid >> 4;
    u64 acc[4][8];
    #pragma unroll
    for (int i = 0; i < 4; i++)
        #pragma unroll
        for (int j = 0; j < 8; j++) acc[i][j] = 0ULL;
    int buf = 0;
    As[0][akq+0][ar] = av.x; As[0][akq+1][ar] = av.y;
    As[0][akq+2][ar] = av.z; As[0][akq+3][ar] = av.w;
    *(float4*)&Bs[0][bkr][bnq] = bv;
    __syncthreads();

    for (int k0 = kbeg; k0 < kend; k0 += 8) {
        bool next = (k0 + 8 < kend);
        if (next) {
            int q1 = k0 + 8;
            kb = q1 >> 8; iQ = (q1 >> 4) & 15; jb = q1 & 8;
            t4 = *(const float4*)&trow[(kb<<4) + jb + akq];
            hv = hrow[(kb<<4) + iQ];
            av = make_float4(hv*t4.x, hv*t4.y, hv*t4.z, hv*t4.w);
            bptr += 8*128;
            bv = *(const float4*)bptr;
        }
        FFMA2_TILE_STEP(As[buf], Bs[buf])
        if (next) {
            int nb = buf ^ 1;
            As[nb][akq+0][ar] = av.x; As[nb][akq+1][ar] = av.y;
            As[nb][akq+2][ar] = av.z; As[nb][akq+3][ar] = av.w;
            *(float4*)&Bs[nb][bkr][bnq] = bv;
            __syncthreads();
            buf = nb;
        }
    }
    // partial layout [m][kc][c]
    #pragma unroll
    for (int i = 0; i < 4; i++) {
        int m = m0 + tm*8 + 2*i;
        if (m < BP) {
            float* row = g_blp + ((long)m*BLKS + kc)*128;
            float4 o0 = make_float4(lo32(acc[i][0]), lo32(acc[i][1]), lo32(acc[i][2]), lo32(acc[i][3]));
            float4 o1 = make_float4(lo32(acc[i][4]), lo32(acc[i][5]), lo32(acc[i][6]), lo32(acc[i][7]));
            *(float4*)&row[tn*8    ] = o0;
            *(float4*)&row[tn*8 + 4] = o1;
        }
        if (m + 1 < BP) {
            float* row = g_blp + ((long)(m+1)*BLKS + kc)*128;
            float4 o0 = make_float4(hi32(acc[i][0]), hi32(acc[i][1]), hi32(acc[i][2]), hi32(acc[i][3]));
            float4 o1 = make_float4(hi32(acc[i][4]), hi32(acc[i][5]), hi32(acc[i][6]), hi32(acc[i][7]));
            *(float4*)&row[tn*8    ] = o0;
            *(float4*)&row[tn*8 + 4] = o1;
        }
    }
}

// ---------------- bilinear reduce ----------------
__global__ void bl_reduce(const float* __restrict__ clsb, float* __restrict__ out)
{
    int m = blockIdx.x;
    int c = threadIdx.x;
    if (c >= NCc) return;
    float s = clsb[c];
    const float* base = g_blp + (long)m*BLKS*128 + c;
    #pragma unroll
    for (int kc = 0; kc < BLKS; kc++)
        s += base[kc*128];
    out[(long)m*NCc + c] = s;
}

// ---------------- launch ----------------
extern "C" void kernel_launch(void* const* d_in, const int* in_sizes, int n_in,
                              void* d_out, int out_size)
{
    const float* seq   = (const float*)d_in[0];
    const float* att   = (const float*)d_in[1];
    const float* headW = (const float*)d_in[2];
    const float* headb = (const float*)d_in[3];
    const float* tailW = (const float*)d_in[4];
    const float* tailb = (const float*)d_in[5];
    const float* projW = (const float*)d_in[6];
    const float* clsW  = (const float*)d_in[7];
    const float* clsb  = (const float*)d_in[8];
    const float* mmask = (const float*)d_in[9];
    const int*   midx  = (const int*)d_in[10];
    const int*   hts   = (const int*)d_in[11];
    float* out = (float*)d_out;

    float *p_ht, *p_rsp, *p_Wcp;
    cudaGetSymbolAddress((void**)&p_ht, g_ht);
    cudaGetSymbolAddress((void**)&p_rsp, g_rsp);
    cudaGetSymbolAddress((void**)&p_Wcp, g_Wcp);

    // Wc partials: cls_W @ proj_W, K-split 2
    {
        dim3 g(1, QQ/128, 2);
        gemm_nn128<<<g, 256>>>(clsW, projW, p_Wcp, NCc, QQ, Hh,
                               0, 0, (long)NCc*QQ, 2);
    }
    // merge + transpose -> g_WcT
    {
        dim3 g(QQ/32, 4), b(32, 8);
        wct_kernel<<<g, b>>>();
    }
    pool_kernel<<<Bb*NEe, 256>>>(seq, att, mmask, midx);
    htatt_kernel<<<Bb*Pp, 256>>>(hts);
    // E partials
    {
        dim3 g(2, Hh/64, 2*EKC);
        e_gemm<<<g, 256>>>(headW, tailW);
    }
    // rs partials: ht[b] @ seq[b], K-split 2 -> [kc][b][p][h]
    {
        dim3 g((Pp + 127)/128, Hh/128, Bb*2);
        gemm_nn128<<<g, 256>>>(p_ht, seq, p_rsp, Pp, Hh, Ls,
                               (long)Pp*Ls, (long)Ls*Hh, (long)Pp*Hh, 2);
    }
    // R[side] = (rsp0+rsp1) @ W2^T
    {
        dim3 g((BP + 127)/128, Hh/128, 2);
        r_gemm<<<g, 256>>>(headW, tailW);
    }
    // hs/ts = tanh(R + E[ent] + b)
    {
        dim3 g(BP, 2);
        fuse_tanh<<<g, 192>>>(headb, tailb, hts);
    }
    // bilinear partials + reduce
    {
        dim3 g((BP + 127)/128, 1, BLKS);
        bilinear_gemm<<<g, 256>>>();
        bl_reduce<<<BP, 128>>>(clsb, out);
    }
}

// round 9
// speedup vs baseline: 1.7403x; 1.7403x over previous
#include <cuda_runtime.h>
#include <cuda_bf16.h>
#include <mma.h>
#include <math.h>

using namespace nvcuda;
typedef __nv_bfloat16 bf16;

#define Bb   4
#define Ls   1024
#define Hh   768
#define NHh  12
#define NEe  30
#define Mm   6
#define Pp   600
#define EMBe 768
#define NCc  97
#define K2H  1536
#define QQ   12288
#define BP   (Bb*Pp)        // 2400
#define BE   (Bb*NEe)       // 120
#define EKC  3
#define BLKS 8
#define PADR 2432           // 19*128 padded pair rows
#define RSR  640            // padded rs rows per batch

// ---------------- scratch ----------------
__device__ float g_e_emb[BE*Hh];
__device__ float g_e_att[BE*NHh*Ls];
__device__ bf16  g_ht_hi[BP*Ls];
__device__ bf16  g_ht_lo[BP*Ls];
__device__ bf16  g_seq_hi[Bb*Ls*Hh];
__device__ bf16  g_seq_lo[Bb*Ls*Hh];
__device__ float g_rs   [Bb*RSR*Hh];
__device__ bf16  g_rs_hi[Bb*RSR*Hh];
__device__ bf16  g_rs_lo[Bb*RSR*Hh];
__device__ bf16  g_W2_hi[2*Hh*Hh];      // [side][n][k] (cols 768.. of head/tail W)
__device__ bf16  g_W2_lo[2*Hh*Hh];
__device__ float g_R    [2*PADR*Hh];
__device__ float g_Ep   [EKC*2*BE*Hh];
__device__ float g_hs   [PADR*EMBe];
__device__ float g_ts   [PADR*EMBe];
__device__ bf16  g_pw_hi[Hh*QQ];
__device__ bf16  g_pw_lo[Hh*QQ];
__device__ bf16  g_cw_hi[NCc*Hh];
__device__ bf16  g_cw_lo[NCc*Hh];
__device__ float g_Wc   [128*QQ];       // padded 128 class rows
__device__ bf16  g_WcT_hi[QQ*128];
__device__ bf16  g_WcT_lo[QQ*128];
__device__ float g_blp  [PADR*BLKS*128];

__device__ __forceinline__ void split1(float v, bf16& h, bf16& l) {
    h = __float2bfloat16_rn(v);
    l = __float2bfloat16_rn(v - __bfloat162float(h));
}

// ---------------- generic fp32 -> (hi,lo) split ----------------
__global__ void split_kernel(const float* __restrict__ in,
                             bf16* __restrict__ hi, bf16* __restrict__ lo, long n)
{
    long i = ((long)blockIdx.x*blockDim.x + threadIdx.x)*4;
    if (i >= n) return;
    float4 v = *(const float4*)&in[i];
    union { bf16 b[4]; uint2 u; } H, L;
    split1(v.x, H.b[0], L.b[0]);
    split1(v.y, H.b[1], L.b[1]);
    split1(v.z, H.b[2], L.b[2]);
    split1(v.w, H.b[3], L.b[3]);
    *(uint2*)&hi[i] = H.u;
    *(uint2*)&lo[i] = L.u;
}

// W2[side][n][k] = (side?tailW:headW)[n*1536 + 768 + k]
__global__ void w2_split(const float* __restrict__ headW, const float* __restrict__ tailW)
{
    int side = blockIdx.y;
    const float* W = side ? tailW : headW;
    long i = ((long)blockIdx.x*blockDim.x + threadIdx.x)*4;
    if (i >= (long)Hh*Hh) return;
    int n = (int)(i / Hh), k = (int)(i % Hh);
    float4 v = *(const float4*)&W[(long)n*K2H + Hh + k];
    union { bf16 b[4]; uint2 u; } H, L;
    split1(v.x, H.b[0], L.b[0]);
    split1(v.y, H.b[1], L.b[1]);
    split1(v.z, H.b[2], L.b[2]);
    split1(v.w, H.b[3], L.b[3]);
    long o = (long)side*Hh*Hh + i;
    *(uint2*)&g_W2_hi[o] = H.u;
    *(uint2*)&g_W2_lo[o] = L.u;
}

// ---------------- entity pooling ----------------
__global__ void pool_kernel(const float* __restrict__ seq,
                            const float* __restrict__ att,
                            const float* __restrict__ mmask,
                            const int*   __restrict__ midx)
{
    int be = blockIdx.x;
    int b = be / NEe;
    __shared__ int   idx[Mm];
    __shared__ float msk[Mm];
    if (threadIdx.x < Mm) {
        idx[threadIdx.x] = midx[be*Mm + threadIdx.x];
        msk[threadIdx.x] = mmask[be*Mm + threadIdx.x];
    }
    __syncthreads();
    float cnt = 0.f;
    #pragma unroll
    for (int m = 0; m < Mm; m++) cnt += msk[m];
    cnt = fmaxf(cnt, 1.0f);
    float invc = 1.0f / cnt;

    for (int h = threadIdx.x; h < Hh; h += blockDim.x) {
        float v[Mm]; float mx = -1e30f;
        #pragma unroll
        for (int m = 0; m < Mm; m++) {
            float x = seq[((long)b*Ls + idx[m])*Hh + h];
            x = (msk[m] > 0.f) ? x : -1e30f;
            v[m] = x; mx = fmaxf(mx, x);
        }
        float s = 0.f;
        #pragma unroll
        for (int m = 0; m < Mm; m++) s += expf(v[m] - mx);
        g_e_emb[(long)be*Hh + h] = mx + logf(s);
    }
    for (int t = threadIdx.x; t < NHh*(Ls/4); t += blockDim.x) {
        int nh = t >> 8, lq = (t & 255)*4;
        float4 s4 = make_float4(0.f,0.f,0.f,0.f);
        #pragma unroll
        for (int m = 0; m < Mm; m++) {
            float4 a = *(const float4*)&att[(((long)b*NHh + nh)*Ls + idx[m])*Ls + lq];
            float w = msk[m];
            s4.x += a.x*w; s4.y += a.y*w; s4.z += a.z*w; s4.w += a.w*w;
        }
        s4.x *= invc; s4.y *= invc; s4.z *= invc; s4.w *= invc;
        *(float4*)&g_e_att[((long)be*NHh + nh)*Ls + lq] = s4;
    }
}

// ---------------- pairwise attention mix -> ht as bf16 hi/lo ----------------
__global__ void htatt_kernel(const int* __restrict__ hts)
{
    int bp = blockIdx.x;
    int b = bp / Pp;
    int he = hts[bp*2 + 0];
    int te = hts[bp*2 + 1];
    const float* ha = &g_e_att[((long)(b*NEe + he))*NHh*Ls];
    const float* ta = &g_e_att[((long)(b*NEe + te))*NHh*Ls];
    __shared__ float sv[Ls];
    __shared__ float red[256];
    int lq = threadIdx.x * 4;
    float4 s4 = make_float4(0.f,0.f,0.f,0.f);
    #pragma unroll
    for (int nh = 0; nh < NHh; nh++) {
        float4 a = *(const float4*)&ha[nh*Ls + lq];
        float4 t = *(const float4*)&ta[nh*Ls + lq];
        s4.x += a.x*t.x; s4.y += a.y*t.y; s4.z += a.z*t.z; s4.w += a.w*t.w;
    }
    const float inh = 1.0f / NHh;
    s4.x *= inh; s4.y *= inh; s4.z *= inh; s4.w *= inh;
    *(float4*)&sv[lq] = s4;
    red[threadIdx.x] = s4.x + s4.y + s4.z + s4.w;
    for (int o = 128; o > 0; o >>= 1) {
        __syncthreads();
        if (threadIdx.x < o) red[threadIdx.x] += red[threadIdx.x + o];
    }
    __syncthreads();
    float inv = 1.0f / (red[0] + 1e-30f);
    float4 v = *(const float4*)&sv[lq];
    v.x *= inv; v.y *= inv; v.z *= inv; v.w *= inv;
    union { bf16 b[4]; uint2 u; } H, L;
    split1(v.x, H.b[0], L.b[0]);
    split1(v.y, H.b[1], L.b[1]);
    split1(v.z, H.b[2], L.b[2]);
    split1(v.w, H.b[3], L.b[3]);
    *(uint2*)&g_ht_hi[(long)bp*Ls + lq] = H.u;
    *(uint2*)&g_ht_lo[(long)bp*Ls + lq] = L.u;
}

// ================= WMMA bf16x3 NN GEMM (generic) =================
// A row-major [Mvalid rows valid, clamp], B row-major [K][N], C fp32 padded.
// 128x128 block, 8 warps (2x4), warp tile 64x32, BK=16, double-buffered.
__global__ __launch_bounds__(256) void wmma_nn(
    const bf16* __restrict__ Ahg, const bf16* __restrict__ Alg, long lda, int Mvalid,
    const bf16* __restrict__ Bhg, const bf16* __restrict__ Blg, long ldb,
    float* __restrict__ Cg, long ldc, int K, long sA, long sB, long sC)
{
    __shared__ __align__(16) bf16 Ah[2][128][16];
    __shared__ __align__(16) bf16 Al[2][128][16];
    __shared__ __align__(16) bf16 Bh[2][16][136];
    __shared__ __align__(16) bf16 Bl[2][16][136];
    int z = blockIdx.z;
    const bf16* Ahp = Ahg + (long)z*sA;
    const bf16* Alp = Alg + (long)z*sA;
    const bf16* Bhp = Bhg + (long)z*sB;
    const bf16* Blp = Blg + (long)z*sB;
    float* Cb = Cg + (long)z*sC;
    int m0 = blockIdx.x*128, n0 = blockIdx.y*128;
    int tid = threadIdx.x;

    int ar = tid>>1, ak = (tid&1)*8;
    int arow = m0 + ar; if (arow > Mvalid-1) arow = Mvalid-1;
    int bk = tid>>4, bn = (tid&15)*8;

    uint4 avh, avl, bvh, bvl;
    int wid = tid>>5, wm = wid>>2, wn = wid&3;
    wmma::fragment<wmma::accumulator,16,16,16,float> acc[4][2];
    #pragma unroll
    for (int mf = 0; mf < 4; mf++)
        #pragma unroll
        for (int nf = 0; nf < 2; nf++) wmma::fill_fragment(acc[mf][nf], 0.f);

    avh = *(const uint4*)(Ahp + (long)arow*lda + ak);
    avl = *(const uint4*)(Alp + (long)arow*lda + ak);
    bvh = *(const uint4*)(Bhp + (long)bk*ldb + n0 + bn);
    bvl = *(const uint4*)(Blp + (long)bk*ldb + n0 + bn);
    *(uint4*)&Ah[0][ar][ak] = avh; *(uint4*)&Al[0][ar][ak] = avl;
    *(uint4*)&Bh[0][bk][bn] = bvh; *(uint4*)&Bl[0][bk][bn] = bvl;
    __syncthreads();
    int buf = 0;

    for (int k0 = 0; k0 < K; k0 += 16) {
        bool nx = (k0 + 16 < K);
        if (nx) {
            avh = *(const uint4*)(Ahp + (long)arow*lda + k0+16 + ak);
            avl = *(const uint4*)(Alp + (long)arow*lda + k0+16 + ak);
            bvh = *(const uint4*)(Bhp + (long)(k0+16+bk)*ldb + n0 + bn);
            bvl = *(const uint4*)(Blp + (long)(k0+16+bk)*ldb + n0 + bn);
        }
        wmma::fragment<wmma::matrix_b,16,16,16,bf16,wmma::row_major> fbh[2], fbl[2];
        #pragma unroll
        for (int nf = 0; nf < 2; nf++) {
            wmma::load_matrix_sync(fbh[nf], &Bh[buf][0][wn*32+nf*16], 136);
            wmma::load_matrix_sync(fbl[nf], &Bl[buf][0][wn*32+nf*16], 136);
        }
        #pragma unroll
        for (int mf = 0; mf < 4; mf++) {
            wmma::fragment<wmma::matrix_a,16,16,16,bf16,wmma::row_major> fah, fal;
            wmma::load_matrix_sync(fah, &Ah[buf][wm*64+mf*16][0], 16);
            wmma::load_matrix_sync(fal, &Al[buf][wm*64+mf*16][0], 16);
            #pragma unroll
            for (int nf = 0; nf < 2; nf++) {
                wmma::mma_sync(acc[mf][nf], fah, fbh[nf], acc[mf][nf]);
                wmma::mma_sync(acc[mf][nf], fah, fbl[nf], acc[mf][nf]);
                wmma::mma_sync(acc[mf][nf], fal, fbh[nf], acc[mf][nf]);
            }
        }
        if (nx) {
            int nb = buf ^ 1;
            *(uint4*)&Ah[nb][ar][ak] = avh; *(uint4*)&Al[nb][ar][ak] = avl;
            *(uint4*)&Bh[nb][bk][bn] = bvh; *(uint4*)&Bl[nb][bk][bn] = bvl;
            __syncthreads();
            buf = nb;
        }
    }
    #pragma unroll
    for (int mf = 0; mf < 4; mf++)
        #pragma unroll
        for (int nf = 0; nf < 2; nf++)
            wmma::store_matrix_sync(&Cb[(long)(m0+wm*64+mf*16)*ldc + n0+wn*32+nf*16],
                                    acc[mf][nf], ldc, wmma::mem_row_major);
}

// ================= R GEMM: (rs pairs) @ W2^T, B col_major =================
__global__ __launch_bounds__(256) void r_wmma()
{
    __shared__ __align__(16) bf16 Ah[2][128][16];
    __shared__ __align__(16) bf16 Al[2][128][16];
    __shared__ __align__(16) bf16 Bh[2][128][16];   // [n][k] col_major frags
    __shared__ __align__(16) bf16 Bl[2][128][16];
    int side = blockIdx.z;
    int m0 = blockIdx.x*128, n0 = blockIdx.y*128;
    int tid = threadIdx.x;
    const bf16* W2h = g_W2_hi + (long)side*Hh*Hh;
    const bf16* W2l = g_W2_lo + (long)side*Hh*Hh;
    float* Cb = g_R + (long)side*PADR*Hh;

    int ar = tid>>1, ak = (tid&1)*8;
    int am = m0 + ar; if (am > BP-1) am = BP-1;
    int b2 = am / Pp, p2 = am % Pp;
    long arowoff = (long)(b2*RSR + p2)*Hh;
    int bn2 = tid>>1, bk2 = (tid&1)*8;

    uint4 avh, avl, bvh, bvl;
    int wid = tid>>5, wm = wid>>2, wn = wid&3;
    wmma::fragment<wmma::accumulator,16,16,16,float> acc[4][2];
    #pragma unroll
    for (int mf = 0; mf < 4; mf++)
        #pragma unroll
        for (int nf = 0; nf < 2; nf++) wmma::fill_fragment(acc[mf][nf], 0.f);

    avh = *(const uint4*)(g_rs_hi + arowoff + ak);
    avl = *(const uint4*)(g_rs_lo + arowoff + ak);
    bvh = *(const uint4*)(W2h + (long)(n0+bn2)*Hh + bk2);
    bvl = *(const uint4*)(W2l + (long)(n0+bn2)*Hh + bk2);
    *(uint4*)&Ah[0][ar][ak] = avh; *(uint4*)&Al[0][ar][ak] = avl;
    *(uint4*)&Bh[0][bn2][bk2] = bvh; *(uint4*)&Bl[0][bn2][bk2] = bvl;
    __syncthreads();
    int buf = 0;

    for (int k0 = 0; k0 < Hh; k0 += 16) {
        bool nx = (k0 + 16 < Hh);
        if (nx) {
            avh = *(const uint4*)(g_rs_hi + arowoff + k0+16 + ak);
            avl = *(const uint4*)(g_rs_lo + arowoff + k0+16 + ak);
            bvh = *(const uint4*)(W2h + (long)(n0+bn2)*Hh + k0+16 + bk2);
            bvl = *(const uint4*)(W2l + (long)(n0+bn2)*Hh + k0+16 + bk2);
        }
        wmma::fragment<wmma::matrix_b,16,16,16,bf16,wmma::col_major> fbh[2], fbl[2];
        #pragma unroll
        for (int nf = 0; nf < 2; nf++) {
            wmma::load_matrix_sync(fbh[nf], &Bh[buf][wn*32+nf*16][0], 16);
            wmma::load_matrix_sync(fbl[nf], &Bl[buf][wn*32+nf*16][0], 16);
        }
        #pragma unroll
        for (int mf = 0; mf < 4; mf++) {
            wmma::fragment<wmma::matrix_a,16,16,16,bf16,wmma::row_major> fah, fal;
            wmma::load_matrix_sync(fah, &Ah[buf][wm*64+mf*16][0], 16);
            wmma::load_matrix_sync(fal, &Al[buf][wm*64+mf*16][0], 16);
            #pragma unroll
            for (int nf = 0; nf < 2; nf++) {
                wmma::mma_sync(acc[mf][nf], fah, fbh[nf], acc[mf][nf]);
                wmma::mma_sync(acc[mf][nf], fah, fbl[nf], acc[mf][nf]);
                wmma::mma_sync(acc[mf][nf], fal, fbh[nf], acc[mf][nf]);
            }
        }
        if (nx) {
            int nb = buf ^ 1;
            *(uint4*)&Ah[nb][ar][ak] = avh; *(uint4*)&Al[nb][ar][ak] = avl;
            *(uint4*)&Bh[nb][bn2][bk2] = bvh; *(uint4*)&Bl[nb][bn2][bk2] = bvl;
            __syncthreads();
            buf = nb;
        }
    }
    #pragma unroll
    for (int mf = 0; mf < 4; mf++)
        #pragma unroll
        for (int nf = 0; nf < 2; nf++)
            wmma::store_matrix_sync(&Cb[(long)(m0+wm*64+mf*16)*Hh + n0+wn*32+nf*16],
                                    acc[mf][nf], Hh, wmma::mem_row_major);
}

// ================= bilinear WMMA: A materialized from hs x ts =================
__global__ __launch_bounds__(256) void bil_wmma()
{
    __shared__ __align__(16) bf16 Ah[2][128][16];
    __shared__ __align__(16) bf16 Al[2][128][16];
    __shared__ __align__(16) bf16 Bh[2][16][136];
    __shared__ __align__(16) bf16 Bl[2][16][136];
    int kc = blockIdx.z;
    int kbeg = kc * (QQ / BLKS), kend = kbeg + (QQ / BLKS);
    int m0 = blockIdx.x*128;
    int tid = threadIdx.x;

    int mA = tid>>1, jq = (tid&1)*8;
    int am = m0 + mA; if (am > BP-1) am = BP-1;
    const float* hrow = g_hs + (long)am*EMBe;
    const float* trow = g_ts + (long)am*EMBe;
    int bk = tid>>4, bn = (tid&15)*8;

    float hval; float4 t0, t1; uint4 bvh, bvl;
    int wid = tid>>5, wm = wid>>2, wn = wid&3;
    wmma::fragment<wmma::accumulator,16,16,16,float> acc[4][2];
    #pragma unroll
    for (int mf = 0; mf < 4; mf++)
        #pragma unroll
        for (int nf = 0; nf < 2; nf++) wmma::fill_fragment(acc[mf][nf], 0.f);

    {
        int kb = kbeg >> 8, iQ = (kbeg >> 4) & 15;
        hval = hrow[(kb<<4) + iQ];
        t0 = *(const float4*)&trow[(kb<<4) + jq];
        t1 = *(const float4*)&trow[(kb<<4) + jq + 4];
        bvh = *(const uint4*)(g_WcT_hi + (long)(kbeg+bk)*128 + bn);
        bvl = *(const uint4*)(g_WcT_lo + (long)(kbeg+bk)*128 + bn);
    }
    {
        float p[8] = {hval*t0.x, hval*t0.y, hval*t0.z, hval*t0.w,
                      hval*t1.x, hval*t1.y, hval*t1.z, hval*t1.w};
        union { bf16 b[8]; uint4 u; } H, L;
        #pragma unroll
        for (int u = 0; u < 8; u++) split1(p[u], H.b[u], L.b[u]);
        *(uint4*)&Ah[0][mA][jq] = H.u;
        *(uint4*)&Al[0][mA][jq] = L.u;
        *(uint4*)&Bh[0][bk][bn] = bvh;
        *(uint4*)&Bl[0][bk][bn] = bvl;
    }
    __syncthreads();
    int buf = 0;

    for (int k0 = kbeg; k0 < kend; k0 += 16) {
        bool nx = (k0 + 16 < kend);
        if (nx) {
            int q1 = k0 + 16;
            int kb = q1 >> 8, iQ = (q1 >> 4) & 15;
            hval = hrow[(kb<<4) + iQ];
            t0 = *(const float4*)&trow[(kb<<4) + jq];
            t1 = *(const float4*)&trow[(kb<<4) + jq + 4];
            bvh = *(const uint4*)(g_WcT_hi + (long)(q1+bk)*128 + bn);
            bvl = *(const uint4*)(g_WcT_lo + (long)(q1+bk)*128 + bn);
        }
        wmma::fragment<wmma::matrix_b,16,16,16,bf16,wmma::row_major> fbh[2], fbl[2];
        #pragma unroll
        for (int nf = 0; nf < 2; nf++) {
            wmma::load_matrix_sync(fbh[nf], &Bh[buf][0][wn*32+nf*16], 136);
            wmma::load_matrix_sync(fbl[nf], &Bl[buf][0][wn*32+nf*16], 136);
        }
        #pragma unroll
        for (int mf = 0; mf < 4; mf++) {
            wmma::fragment<wmma::matrix_a,16,16,16,bf16,wmma::row_major> fah, fal;
            wmma::load_matrix_sync(fah, &Ah[buf][wm*64+mf*16][0], 16);
            wmma::load_matrix_sync(fal, &Al[buf][wm*64+mf*16][0], 16);
            #pragma unroll
            for (int nf = 0; nf < 2; nf++) {
                wmma::mma_sync(acc[mf][nf], fah, fbh[nf], acc[mf][nf]);
                wmma::mma_sync(acc[mf][nf], fah, fbl[nf], acc[mf][nf]);
                wmma::mma_sync(acc[mf][nf], fal, fbh[nf], acc[mf][nf]);
            }
        }
        if (nx) {
            int nb = buf ^ 1;
            float p[8] = {hval*t0.x, hval*t0.y, hval*t0.z, hval*t0.w,
                          hval*t1.x, hval*t1.y, hval*t1.z, hval*t1.w};
            union { bf16 b[8]; uint4 u; } H, L;
            #pragma unroll
            for (int u = 0; u < 8; u++) split1(p[u], H.b[u], L.b[u]);
            *(uint4*)&Ah[nb][mA][jq] = H.u;
            *(uint4*)&Al[nb][mA][jq] = L.u;
            *(uint4*)&Bh[nb][bk][bn] = bvh;
            *(uint4*)&Bl[nb][bk][bn] = bvl;
            __syncthreads();
            buf = nb;
        }
    }
    // partials [m][kc][c], ldm = BLKS*128
    #pragma unroll
    for (int mf = 0; mf < 4; mf++)
        #pragma unroll
        for (int nf = 0; nf < 2; nf++)
            wmma::store_matrix_sync(
                &g_blp[((long)(m0+wm*64+mf*16)*BLKS + kc)*128 + wn*32+nf*16],
                acc[mf][nf], BLKS*128, wmma::mem_row_major);
}

// ---------------- Wc transpose + split ----------------
__global__ void wct_kernel()
{
    __shared__ float sm[32][33];
    int q0 = blockIdx.x * 32;
    int c0 = blockIdx.y * 32;
    int tx = threadIdx.x, ty = threadIdx.y;    // (32, 8)
    #pragma unroll
    for (int u = 0; u < 4; u++) {
        int c = c0 + ty + u*8;
        float v = 0.f;
        if (c < NCc) v = g_Wc[(long)c*QQ + q0 + tx];
        sm[ty + u*8][tx] = v;
    }
    __syncthreads();
    #pragma unroll
    for (int u = 0; u < 4; u++) {
        int q = q0 + ty + u*8;
        float v = sm[tx][ty + u*8];
        bf16 h, l; split1(v, h, l);
        g_WcT_hi[(long)q*128 + c0 + tx] = h;
        g_WcT_lo[(long)q*128 + c0 + tx] = l;
    }
}

// ---------------- E GEMM (scalar, small) ----------------
__global__ __launch_bounds__(256) void e_gemm(
    const float* __restrict__ headW, const float* __restrict__ tailW)
{
    __shared__ float As[16][65];
    __shared__ float Bs[16][65];
    int z = blockIdx.z;
    int side = z & 1, kc = z >> 1;
    const float* W = side ? tailW : headW;
    float* Cb = g_Ep + (long)(kc*2 + side)*BE*Hh;
    int m0 = blockIdx.x*64, n0 = blockIdx.y*64;
    int tid = threadIdx.x;
    int tm = tid & 15, tn = tid >> 4;
    float acc[4][4] = {};
    int kbeg = kc*256, kend = kbeg + 256;
    for (int k0 = kbeg; k0 < kend; k0 += 16) {
        #pragma unroll
        for (int i = 0; i < 4; i++) {
            int idx = tid + i*256;
            int m = idx >> 4, k = idx & 15;
            int mg = m0 + m; if (mg > BE-1) mg = BE-1;
            As[k][m] = g_e_emb[(long)mg*Hh + k0 + k];
        }
        #pragma unroll
        for (int i = 0; i < 4; i++) {
            int idx = tid + i*256;
            int e = idx >> 4, k = idx & 15;
            Bs[k][e] = W[(long)(n0 + e)*K2H + k0 + k];
        }
        __syncthreads();
        #pragma unroll
        for (int kk = 0; kk < 16; kk++) {
            float a[4], bb[4];
            #pragma unroll
            for (int i = 0; i < 4; i++) a[i]  = As[kk][tm + 16*i];
            #pragma unroll
            for (int j = 0; j < 4; j++) bb[j] = Bs[kk][tn + 16*j];
            #pragma unroll
            for (int i = 0; i < 4; i++)
                #pragma unroll
                for (int j = 0; j < 4; j++)
                    acc[i][j] += a[i]*bb[j];
        }
        __syncthreads();
    }
    #pragma unroll
    for (int i = 0; i < 4; i++) {
        int m = m0 + tm + 16*i;
        if (m >= BE) continue;
        #pragma unroll
        for (int j = 0; j < 4; j++)
            Cb[(long)m*Hh + n0 + tn + 16*j] = acc[i][j];
    }
}

// ---------------- fused gather + add + tanh ----------------
__global__ void fuse_tanh(const float* __restrict__ headb,
                          const float* __restrict__ tailb,
                          const int*   __restrict__ hts)
{
    int m = blockIdx.x, side = blockIdx.y;
    int b = m / Pp;
    int ent = hts[m*2 + side];
    int er = b*NEe + ent;
    const float* Rr   = g_R + ((long)side*PADR + m)*Hh;
    const float* bias = side ? tailb : headb;
    float* outp = (side ? g_ts : g_hs) + (long)m*EMBe;
    const float* e0 = g_Ep + (long)(0*2 + side)*BE*Hh + (long)er*Hh;
    const float* e1 = g_Ep + (long)(1*2 + side)*BE*Hh + (long)er*Hh;
    const float* e2 = g_Ep + (long)(2*2 + side)*BE*Hh + (long)er*Hh;
    int e = threadIdx.x * 4;
    float4 r  = *(const float4*)&Rr[e];
    float4 p0 = *(const float4*)&e0[e];
    float4 p1 = *(const float4*)&e1[e];
    float4 p2 = *(const float4*)&e2[e];
    float4 bi = *(const float4*)&bias[e];
    float4 o;
    o.x = tanhf(r.x + p0.x + p1.x + p2.x + bi.x);
    o.y = tanhf(r.y + p0.y + p1.y + p2.y + bi.y);
    o.z = tanhf(r.z + p0.z + p1.z + p2.z + bi.z);
    o.w = tanhf(r.w + p0.w + p1.w + p2.w + bi.w);
    *(float4*)&outp[e] = o;
}

// ---------------- bilinear reduce ----------------
__global__ void bl_reduce(const float* __restrict__ clsb, float* __restrict__ out)
{
    int m = blockIdx.x;
    int c = threadIdx.x;
    if (c >= NCc) return;
    float s = clsb[c];
    const float* base = g_blp + (long)m*BLKS*128 + c;
    #pragma unroll
    for (int kc = 0; kc < BLKS; kc++)
        s += base[kc*128];
    out[(long)m*NCc + c] = s;
}

// ---------------- launch ----------------
extern "C" void kernel_launch(void* const* d_in, const int* in_sizes, int n_in,
                              void* d_out, int out_size)
{
    const float* seq   = (const float*)d_in[0];
    const float* att   = (const float*)d_in[1];
    const float* headW = (const float*)d_in[2];
    const float* headb = (const float*)d_in[3];
    const float* tailW = (const float*)d_in[4];
    const float* tailb = (const float*)d_in[5];
    const float* projW = (const float*)d_in[6];
    const float* clsW  = (const float*)d_in[7];
    const float* clsb  = (const float*)d_in[8];
    const float* mmask = (const float*)d_in[9];
    const int*   midx  = (const int*)d_in[10];
    const int*   hts   = (const int*)d_in[11];
    float* out = (float*)d_out;

    bf16 *p_pwh, *p_pwl, *p_cwh, *p_cwl, *p_seqh, *p_seql;
    bf16 *p_hth, *p_htl, *p_rsh, *p_rsl;
    float *p_rs, *p_Wc;
    cudaGetSymbolAddress((void**)&p_pwh, g_pw_hi);
    cudaGetSymbolAddress((void**)&p_pwl, g_pw_lo);
    cudaGetSymbolAddress((void**)&p_cwh, g_cw_hi);
    cudaGetSymbolAddress((void**)&p_cwl, g_cw_lo);
    cudaGetSymbolAddress((void**)&p_seqh, g_seq_hi);
    cudaGetSymbolAddress((void**)&p_seql, g_seq_lo);
    cudaGetSymbolAddress((void**)&p_hth, g_ht_hi);
    cudaGetSymbolAddress((void**)&p_htl, g_ht_lo);
    cudaGetSymbolAddress((void**)&p_rsh, g_rs_hi);
    cudaGetSymbolAddress((void**)&p_rsl, g_rs_lo);
    cudaGetSymbolAddress((void**)&p_rs, g_rs);
    cudaGetSymbolAddress((void**)&p_Wc, g_Wc);

    // input splits
    {
        long n = (long)Hh*QQ;
        split_kernel<<<(unsigned)((n/4 + 255)/256), 256>>>(projW, p_pwh, p_pwl, n);
    }
    {
        long n = (long)NCc*Hh;
        split_kernel<<<(unsigned)((n/4 + 255)/256), 256>>>(clsW, p_cwh, p_cwl, n);
    }
    {
        long n = (long)Bb*Ls*Hh;
        split_kernel<<<(unsigned)((n/4 + 255)/256), 256>>>(seq, p_seqh, p_seql, n);
    }
    {
        long n = (long)Hh*Hh;
        dim3 g((unsigned)((n/4 + 255)/256), 2);
        w2_split<<<g, 256>>>(headW, tailW);
    }

    // Wc = cls_W @ proj_W  (M=97 pad 128, N=12288, K=768)
    {
        dim3 g(1, QQ/128, 1);
        wmma_nn<<<g, 256>>>(p_cwh, p_cwl, Hh, NCc,
                            p_pwh, p_pwl, QQ,
                            p_Wc, QQ, Hh, 0, 0, 0);
    }
    {
        dim3 g(QQ/32, 4), b(32, 8);
        wct_kernel<<<g, b>>>();
    }

    pool_kernel<<<Bb*NEe, 256>>>(seq, att, mmask, midx);
    htatt_kernel<<<Bb*Pp, 256>>>(hts);
    {
        dim3 g(2, Hh/64, 2*EKC);
        e_gemm<<<g, 256>>>(headW, tailW);
    }

    // rs[b] = ht[b] @ seq[b]  (M=600 pad 640, N=768, K=1024)
    {
        dim3 g(5, Hh/128, Bb);
        wmma_nn<<<g, 256>>>(p_hth, p_htl, Ls, Pp,
                            p_seqh, p_seql, Hh,
                            p_rs, Hh, Ls,
                            (long)Pp*Ls, (long)Ls*Hh, (long)RSR*Hh);
    }
    // split rs (incl. padded garbage rows — never read)
    {
        long n = (long)Bb*RSR*Hh;
        split_kernel<<<(unsigned)((n/4 + 255)/256), 256>>>(p_rs, p_rsh, p_rsl, n);
    }
    // R[side] = rs @ W2^T  (M=2400 pad 2432, N=768, K=768)
    {
        dim3 g(PADR/128, Hh/128, 2);
        r_wmma<<<g, 256>>>();
    }
    // hs/ts = tanh(R + E[ent] + b)
    {
        dim3 g(BP, 2);
        fuse_tanh<<<g, 192>>>(headb, tailb, hts);
    }
    // bilinear partials + reduce
    {
        dim3 g(PADR/128, 1, BLKS);
        bil_wmma<<<g, 256>>>();
        bl_reduce<<<BP, 128>>>(clsb, out);
    }
}